// round 15
// baseline (speedup 1.0000x reference)
#include <cuda_runtime.h>
#include <cuda_bf16.h>
#include <cstdint>

#define N_BANDS    128
#define RESO       64
#define N_FRAMES   128
#define N_SAMPLES  32768
#define BATCH      16
#define N_ROWS     (BATCH * N_BANDS)

typedef unsigned long long u64;

// Pair table: g_framep[i*2048 + c*16 + b] = (frames[b,c,i], frames[b,c,min(i+1,127)])
__device__ __align__(16) float2 g_framep[N_FRAMES * N_ROWS];

__device__ __forceinline__ u64 fma2(u64 a, u64 b, u64 c) {
    u64 d;
    asm("fma.rn.f32x2 %0, %1, %2, %3;" : "=l"(d) : "l"(a), "l"(b), "l"(c));
    return d;
}
__device__ __forceinline__ u64 add2(u64 a, u64 b) {
    u64 d;
    asm("add.rn.f32x2 %0, %1, %2;" : "=l"(d) : "l"(a), "l"(b));
    return d;
}
__device__ __forceinline__ u64 dup32(float x) {
    u64 r;
    unsigned int xi = __float_as_uint(x);
    asm("mov.b64 %0, {%1, %1};" : "=l"(r) : "r"(xi));
    return r;
}
__device__ __forceinline__ float u64lo(u64 v) {
    return __uint_as_float((unsigned int)(v & 0xFFFFFFFFull));
}
__device__ __forceinline__ float u64hi(u64 v) {
    return __uint_as_float((unsigned int)(v >> 32));
}

// ---------------------------------------------------------------------------
// Kernel 1: 128 blocks (block = band c) x 512 threads.
// r-dimension split across two 256-thread halves -> 16 (not 32) serial
// matmul iterations per thread and 16 warps/SM for latency hiding.
// Halves combined via payload-major smem scratch. Coalesced pair writes.
// ---------------------------------------------------------------------------
__global__ __launch_bounds__(512)
void frames_kernel(const float* __restrict__ x,
                   const float* __restrict__ reso) {
    __shared__ float resT[N_FRAMES * 66];   // [f][r] padded stride 66 (33.8KB)
    __shared__ float xs[1024];               // [b*64 + r]
    __shared__ float ps[16 * 66];            // [b*66 + r] padded
    __shared__ float scratch[2048];          // half-sum scratch; later fr[]

    const int tid = threadIdx.x;
    const int c = blockIdx.x;

    // Stage resonance transposed: resT[f*66 + r] = reso[r*128 + f]
    for (int idx = tid; idx < RESO * N_FRAMES; idx += 512) {
        const int r = idx >> 7;
        const int f = idx & 127;
        resT[f * 66 + r] = reso[idx];
    }
    // Stage x rows (b = 0..15 at fixed c).
    for (int idx = tid; idx < 16 * RESO; idx += 512) {
        const int b = idx >> 6;
        const int r = idx & 63;
        xs[idx] = x[(b * 128 + c) * RESO + r];
    }
    __syncthreads();

    // Softmax: 16 warps, warp w handles row w.
    {
        const int w = tid >> 5;
        const int lane = tid & 31;
        if (w < 16) {
            float v0 = xs[w * 64 + lane];
            float v1 = xs[w * 64 + lane + 32];
            float m = fmaxf(v0, v1);
            #pragma unroll
            for (int off = 16; off > 0; off >>= 1)
                m = fmaxf(m, __shfl_xor_sync(0xFFFFFFFFu, m, off));
            float e0 = __expf(v0 - m);
            float e1 = __expf(v1 - m);
            float s = e0 + e1;
            #pragma unroll
            for (int off = 16; off > 0; off >>= 1)
                s += __shfl_xor_sync(0xFFFFFFFFu, s, off);
            float inv = 1.0f / s;
            ps[w * 66 + lane]      = e0 * inv;
            ps[w * 66 + lane + 32] = e1 * inv;
        }
    }
    __syncthreads();

    // Matmul over half the r range: thread = (b, f0, rh); 16 r-pair iters.
    const int b  = tid & 15;
    const int f0 = (tid >> 4) & 15;
    const int rh = tid >> 8;             // 0 or 1
    const int t256 = tid & 255;

    float v[8];
    {
        u64 acc2[8];
        #pragma unroll
        for (int i = 0; i < 8; ++i) acc2[i] = 0ull;

        const int rrbase = rh * 16;
        #pragma unroll 4
        for (int rr = 0; rr < 16; ++rr) {
            const u64 psp = *reinterpret_cast<const u64*>(
                &ps[b * 66 + 2 * (rrbase + rr)]);
            #pragma unroll
            for (int i = 0; i < 8; ++i) {
                const u64 rp = *reinterpret_cast<const u64*>(
                    &resT[(f0 + 16 * i) * 66 + 2 * (rrbase + rr)]);
                acc2[i] = fma2(rp, psp, acc2[i]);
            }
        }
        #pragma unroll
        for (int i = 0; i < 8; ++i) v[i] = u64lo(acc2[i]) + u64hi(acc2[i]);
    }

    // Combine halves: rh=1 stores payload-major (conflict-free), rh=0 adds.
    if (rh == 1) {
        #pragma unroll
        for (int i = 0; i < 8; ++i) scratch[i * 256 + t256] = v[i];
    }
    __syncthreads();
    if (rh == 0) {
        #pragma unroll
        for (int i = 0; i < 8; ++i) v[i] += scratch[i * 256 + t256];
    }
    __syncthreads();   // scratch consumed; reuse as fr[]

    float* fr = scratch;   // [f*16 + b], 2048 floats
    if (rh == 0) {
        #pragma unroll
        for (int i = 0; i < 8; ++i)
            fr[(f0 + 16 * i) * 16 + b] = v[i];
    }
    __syncthreads();

    // Coalesced pair-table writes (256 threads).
    if (rh == 0) {
        #pragma unroll
        for (int k = 0; k < 8; ++k) {
            const int p = f0 + 16 * k;
            const int pn = (p + 1 < N_FRAMES) ? p + 1 : N_FRAMES - 1;
            const float lo = fr[p * 16 + b];
            const float hi = fr[pn * 16 + b];
            g_framep[p * N_ROWS + c * 16 + b] = make_float2(lo, hi);
        }
    }

    __threadfence();
    asm volatile("griddepcontrol.launch_dependents;");
}

// ---------------------------------------------------------------------------
// Kernel 2 (PDL-launched): identical to round 14 (stable 13.4us).
// ---------------------------------------------------------------------------
__global__ __launch_bounds__(256, 4)
void mix_kernel(const float* __restrict__ fb,
                float* __restrict__ out) {
    __shared__ __align__(16) float fbbuf[4 * 2048];   // 32 KB, 4 chunks
    __shared__ __align__(16) u64 FPs[N_ROWS];         // 16 KB pair table

    const int tid = threadIdx.x;
    const int n = blockIdx.x;
    const int s_base = n * 64;

    const int i0 = (n < 2) ? 0 : ((n - 2) >> 2);

    const unsigned int fb_s0 = (unsigned int)__cvta_generic_to_shared(&fbbuf[0]);
    const unsigned int FP_s0 = (unsigned int)__cvta_generic_to_shared(&FPs[0]);

#define STAGE_FB(CHUNK)                                                       \
    {                                                                         \
        _Pragma("unroll")                                                     \
        for (int i = 0; i < 2; ++i) {                                         \
            const int o = (i * 256 + tid) * 16;                               \
            const int band = o >> 8;                                          \
            const int within = o & 255;                                       \
            const float* g = fb + ((CHUNK) * 32 + band) * N_SAMPLES           \
                               + s_base + (within >> 2);                      \
            asm volatile("cp.async.cg.shared.global [%0], [%1], 16;\n"        \
                         :: "r"(fb_s0 + (CHUNK) * 8192 + o), "l"(g));         \
        }                                                                     \
        asm volatile("cp.async.commit_group;\n");                             \
    }

    STAGE_FB(1);
    STAGE_FB(2);
    STAGE_FB(3);

    asm volatile("griddepcontrol.wait;" ::: "memory");
    {
        const char* gp = (const char*)(g_framep + i0 * N_ROWS);
        #pragma unroll
        for (int i = 0; i < 4; ++i) {
            const int o = (i * 256 + tid) * 16;
            asm volatile("cp.async.cg.shared.global [%0], [%1], 16;\n"
                         :: "r"(FP_s0 + o), "l"(gp + o));
        }
        #pragma unroll
        for (int i = 0; i < 2; ++i) {
            const int o = (i * 256 + tid) * 16;
            const int band = o >> 8;
            const int within = o & 255;
            const float* g = fb + band * N_SAMPLES + s_base + (within >> 2);
            asm volatile("cp.async.cg.shared.global [%0], [%1], 16;\n"
                         :: "r"(fb_s0 + o), "l"(g));
        }
        asm volatile("cp.async.commit_group;\n");
    }

    const int sg = tid & 15;             // 4-sample group
    const int bq = (tid >> 4) & 7;       // batch pair (batches 2bq, 2bq+1)
    const int bs = tid >> 7;             // band half (16 of each 32-chunk)

    u64 acc[8];
    #pragma unroll
    for (int p = 0; p < 8; ++p) acc[p] = 0ull;

#define PROC(CH)                                                              \
    {                                                                         \
        _Pragma("unroll 4")                                                   \
        for (int cl = 0; cl < 16; ++cl) {                                     \
            const int cb = bs * 16 + cl;                                      \
            const int c  = (CH) * 32 + cb;                                    \
            const float4 fv = *reinterpret_cast<const float4*>(               \
                &fbbuf[(CH) * 2048 + cb * 64 + sg * 4]);                      \
            const u64 d0 = dup32(fv.x);                                       \
            const u64 d1 = dup32(fv.y);                                       \
            const u64 d2 = dup32(fv.z);                                       \
            const u64 d3 = dup32(fv.w);                                       \
            const ulonglong2 fp2 = *reinterpret_cast<const ulonglong2*>(      \
                &FPs[c * 16 + bq * 2]);                                       \
            acc[0] = fma2(fp2.x, d0, acc[0]);                                 \
            acc[1] = fma2(fp2.x, d1, acc[1]);                                 \
            acc[2] = fma2(fp2.x, d2, acc[2]);                                 \
            acc[3] = fma2(fp2.x, d3, acc[3]);                                 \
            acc[4] = fma2(fp2.y, d0, acc[4]);                                 \
            acc[5] = fma2(fp2.y, d1, acc[5]);                                 \
            acc[6] = fma2(fp2.y, d2, acc[6]);                                 \
            acc[7] = fma2(fp2.y, d3, acc[7]);                                 \
        }                                                                     \
    }

    asm volatile("cp.async.wait_group 0;\n" ::: "memory");
    __syncthreads();
    PROC(0);
    PROC(1);
    PROC(2);
    PROC(3);

#undef STAGE_FB
#undef PROC

    __syncthreads();
    u64* S = reinterpret_cast<u64*>(&fbbuf[0]);
    if (tid >= 128) {
        const int j = tid - 128;
        #pragma unroll
        for (int p = 0; p < 8; ++p) S[p * 128 + j] = acc[p];
    }
    __syncthreads();
    if (tid < 128) {
        const int s0 = s_base + sg * 4;
        float w[4];
        #pragma unroll
        for (int j = 0; j < 4; ++j) {
            float pos = (float)(s0 + j) * (1.0f / 256.0f)
                        + (0.5f / 256.0f - 0.5f);
            pos = fminf(fmaxf(pos, 0.0f), 127.0f);
            w[j] = pos - floorf(pos);
        }
        #pragma unroll
        for (int bp = 0; bp < 2; ++bp) {
            float4 o;
            float* ov = &o.x;
            #pragma unroll
            for (int j = 0; j < 4; ++j) {
                const u64 A = add2(acc[bp * 4 + j],
                                   S[(bp * 4 + j) * 128 + tid]);
                const float a0 = u64lo(A);
                const float a1 = u64hi(A);
                ov[j] = fmaf(w[j], a1 - a0, a0) * (1.0f / 128.0f);
            }
            *reinterpret_cast<float4*>(
                out + (bq * 2 + bp) * N_SAMPLES + s0) = o;
        }
    }
}

// ---------------------------------------------------------------------------
extern "C" void kernel_launch(void* const* d_in, const int* in_sizes, int n_in,
                              void* d_out, int out_size) {
    const float* x = nullptr;      // (16,128,64)    = 131072
    const float* reso = nullptr;   // (64,128)       = 8192
    const float* fb = nullptr;     // (1,128,32768)  = 4194304
    for (int i = 0; i < n_in; ++i) {
        if (in_sizes[i] == BATCH * N_BANDS * RESO)      x = (const float*)d_in[i];
        else if (in_sizes[i] == RESO * N_FRAMES)        reso = (const float*)d_in[i];
        else if (in_sizes[i] == N_BANDS * N_SAMPLES)    fb = (const float*)d_in[i];
    }
    float* out = (float*)d_out;

    frames_kernel<<<N_BANDS, 512>>>(x, reso);

    cudaLaunchConfig_t cfg = {};
    cfg.gridDim = dim3(N_SAMPLES / 64);
    cfg.blockDim = dim3(256);
    cfg.dynamicSmemBytes = 0;
    cfg.stream = 0;
    cudaLaunchAttribute attrs[1];
    attrs[0].id = cudaLaunchAttributeProgrammaticStreamSerialization;
    attrs[0].val.programmaticStreamSerializationAllowed = 1;
    cfg.attrs = attrs;
    cfg.numAttrs = 1;
    cudaLaunchKernelEx(&cfg, mix_kernel, fb, out);
}